// round 2
// baseline (speedup 1.0000x reference)
#include <cuda_runtime.h>
#include <cuda_bf16.h>

// ApproxNDCGLoss: loss = 1 - dcg/(idcg+1e-8), guarded by sum(y) < 1.
//   approx_rank[j] = 1 + sum_i sigmoid(s[j] - s[i])
//   dcg  = sum_j y[j] / log2(approx_rank[j] + 1)
//   idcg = sum_r sorted_desc(y)[r] / log2(r + 2)
//        = sum_j y[j] / log2(exact_desc_rank(y[j]) + 2)
//   exact_desc_rank(y[j]) = 1 + #{i: y_i > y_j} + #{i<j: y_i == y_j}
//   (stable descending sort; tied values are equal so any consistent
//    assignment of consecutive discounts within a tie group is exact)
//
// sigmoid via single MUFU.TANH: sigmoid(x) = 0.5 + 0.5*tanh(0.5*x).

#define TPB    256
#define TILE   2048
#define SPLIT  10
#define MAXN   20480
#define MAXSPL 16
#define MAXBLK 160

__device__ float g_rankP[MAXSPL * MAXN];  // per-split partial sigmoid sums
__device__ int   g_gtP  [MAXSPL * MAXN];  // per-split rank counts
__device__ float g_dcgP [MAXBLK];
__device__ float g_idcgP[MAXBLK];
__device__ float g_sumyP[MAXBLK];

__device__ __forceinline__ float tanh_approx(float x) {
    float r;
    asm("tanh.approx.f32 %0, %1;" : "=f"(r) : "f"(x));
    return r;
}

// ---------------------------------------------------------------------------
// K1: pairwise pass. blockIdx.x tiles j; blockIdx.y = i-range split.
// Each thread owns one j; i streams through shared tiles (broadcast LDS).
// ---------------------------------------------------------------------------
__global__ void __launch_bounds__(TPB)
k1_pairwise(const float* __restrict__ s, const float* __restrict__ y,
            int n, int chunk)
{
    const int j     = blockIdx.x * TPB + threadIdx.x;
    const int split = blockIdx.y;
    const int i0 = split * chunk;
    const int i1 = min(i0 + chunk, n);

    __shared__ float ssh[TILE];   // 0.5 * s[i]
    __shared__ float sy [TILE];   // y[i]

    const float sjh = (j < n) ? 0.5f * s[j] : 0.0f;
    const float yj  = (j < n) ? y[j] : 0.0f;

    float acc = 0.0f;   // sum of tanh(0.5*(s_j - s_i))
    int   cnt = 0;      // rank count

    for (int base = i0; base < i1; base += TILE) {
        const int len = min(TILE, i1 - base);
        __syncthreads();
        for (int t = threadIdx.x; t < len; t += TPB) {
            ssh[t] = 0.5f * s[base + t];
            sy [t] = y[base + t];
        }
        __syncthreads();

        const int t0 = j - base;   // i < j  <=>  t < t0

        #pragma unroll 8
        for (int t = 0; t < len; t++) {
            acc += tanh_approx(sjh - ssh[t]);          // FSUB + MUFU.TANH + FADD
            float yi = sy[t];
            cnt += (yi > yj) || (yi == yj && t < t0);  // FSETP chain + IADD
        }
    }

    if (j < n) {
        // sum_i sigmoid = 0.5*len_total + 0.5*acc
        g_rankP[split * MAXN + j] = 0.5f * (float)(i1 - i0) + 0.5f * acc;
        g_gtP  [split * MAXN + j] = cnt;
    }
}

// ---------------------------------------------------------------------------
// K2: per-j finalize + deterministic block reduction into per-block partials.
// ---------------------------------------------------------------------------
__global__ void __launch_bounds__(TPB)
k2_finalize(const float* __restrict__ y, int n)
{
    const int j = blockIdx.x * TPB + threadIdx.x;

    float dcg = 0.0f, idcg = 0.0f, sumy = 0.0f;
    if (j < n) {
        float acc = 0.0f;
        int   cnt = 0;
        #pragma unroll
        for (int sp = 0; sp < SPLIT; sp++) {
            acc += g_rankP[sp * MAXN + j];
            cnt += g_gtP  [sp * MAXN + j];
        }
        const float rank = 1.0f + acc;          // approx rank (i==j gives 0.5)
        const float yj   = y[j];
        dcg  = yj / __log2f(rank + 1.0f);
        idcg = yj / __log2f((float)(cnt + 2));  // ideal_rank = cnt+1
        sumy = yj;
    }

    __shared__ float rd[TPB], ri[TPB], rs[TPB];
    rd[threadIdx.x] = dcg; ri[threadIdx.x] = idcg; rs[threadIdx.x] = sumy;
    __syncthreads();
    for (int off = TPB / 2; off > 0; off >>= 1) {
        if (threadIdx.x < off) {
            rd[threadIdx.x] += rd[threadIdx.x + off];
            ri[threadIdx.x] += ri[threadIdx.x + off];
            rs[threadIdx.x] += rs[threadIdx.x + off];
        }
        __syncthreads();
    }
    if (threadIdx.x == 0) {
        g_dcgP [blockIdx.x] = rd[0];
        g_idcgP[blockIdx.x] = ri[0];
        g_sumyP[blockIdx.x] = rs[0];
    }
}

// ---------------------------------------------------------------------------
// K3: final single-block reduction + loss.
// ---------------------------------------------------------------------------
__global__ void __launch_bounds__(TPB)
k3_loss(float* __restrict__ out, int nblk)
{
    __shared__ float rd[TPB], ri[TPB], rs[TPB];
    float d = 0.0f, i = 0.0f, sY = 0.0f;
    for (int b = threadIdx.x; b < nblk; b += TPB) {
        d  += g_dcgP[b];
        i  += g_idcgP[b];
        sY += g_sumyP[b];
    }
    rd[threadIdx.x] = d; ri[threadIdx.x] = i; rs[threadIdx.x] = sY;
    __syncthreads();
    for (int off = TPB / 2; off > 0; off >>= 1) {
        if (threadIdx.x < off) {
            rd[threadIdx.x] += rd[threadIdx.x + off];
            ri[threadIdx.x] += ri[threadIdx.x + off];
            rs[threadIdx.x] += rs[threadIdx.x + off];
        }
        __syncthreads();
    }
    if (threadIdx.x == 0) {
        float ndcg = rd[0] / (ri[0] + 1e-8f);
        float loss = 1.0f - ndcg;
        out[0] = (rs[0] < 1.0f) ? 0.0f : loss;
    }
}

// ---------------------------------------------------------------------------
extern "C" void kernel_launch(void* const* d_in, const int* in_sizes, int n_in,
                              void* d_out, int out_size)
{
    const float* s = (const float*)d_in[0];   // logits
    const float* y = (const float*)d_in[1];   // targets
    float* out = (float*)d_out;
    const int n = in_sizes[0];

    const int jblocks = (n + TPB - 1) / TPB;
    const int chunk   = (n + SPLIT - 1) / SPLIT;

    dim3 g1(jblocks, SPLIT);
    k1_pairwise<<<g1, TPB>>>(s, y, n, chunk);
    k2_finalize<<<jblocks, TPB>>>(y, n);
    k3_loss<<<1, TPB>>>(out, jblocks);
}

// round 3
// speedup vs baseline: 3.3988x; 3.3988x over previous
#include <cuda_runtime.h>
#include <cuda_bf16.h>

// ApproxNDCGLoss via histogram convolution (O(N*G)) instead of O(N^2) pairs.
//
//   approx_rank[j] = 1 + sum_i sigmoid(s_j - s_i)
//                  ~ 1 + sum_g [ H_g*sig(s_j - c_g) - S1_g*sig'(s_j - c_g) ]
//     where H_g = #{i in bin g}, S1_g = sum_{i in g} (s_i - c_g)   (1st-order
//     Taylor per bin; 2nd-order remainder ~0.01 rank units for h~0.0063).
//
//   dcg  = sum_j y_j / log2(rank_j + 1)
//   idcg = sum over exact descending ranks of y: counting-rank over a 65536-bin
//          histogram of y in [0,1); per-bin exact starting rank from an exact
//          integer suffix scan; single-occupancy bins are exact, multi bins use
//          bin-mean y (error ~2^-16 * discount step, negligible).
//   loss = (sum(y) < 1) ? 0 : 1 - dcg/(idcg + 1e-8)

#define TPB     256
#define G       2048
#define GSPLIT  4
#define GCHUNK  (G / GSPLIT)      // 512
#define YB      65536
#define YBLK    64                // YB / 1024
#define MAXN    32768
#define MAXJB   128

#define S_LO   (-6.5f)
#define S_HI   ( 6.5f)

__device__ float g_SH  [2 * G];        // interleaved {count, moment} per s-bin
__device__ float g_YC  [YB];           // y-bin counts (exact integers in f32)
__device__ float g_YS  [YB];           // y-bin value sums
__device__ float g_CS  [YBLK];         // per-1024-chunk count sums
__device__ float g_CSX [YBLK];         // exclusive suffix of chunk sums
__device__ float g_rankP[GSPLIT * MAXN];
__device__ float g_dcgP [MAXJB];
__device__ float g_idcgP[YBLK];
__device__ float g_sumyP[YBLK];

__device__ __forceinline__ float tanh_approx(float x) {
    float r;
    asm("tanh.approx.f32 %0, %1;" : "=f"(r) : "f"(x));
    return r;
}

// --------------------------------------------------------------------------
__global__ void k_zero()
{
    const int tid = blockIdx.x * blockDim.x + threadIdx.x;
    const int stride = gridDim.x * blockDim.x;
    for (int i = tid; i < 2 * G; i += stride) g_SH[i] = 0.0f;
    for (int i = tid; i < YB; i += stride) { g_YC[i] = 0.0f; g_YS[i] = 0.0f; }
}

// --------------------------------------------------------------------------
__global__ void k_hist(const float* __restrict__ s, const float* __restrict__ y,
                       int n)
{
    const int j = blockIdx.x * blockDim.x + threadIdx.x;
    if (j >= n) return;

    const float h     = (S_HI - S_LO) / (float)G;
    const float inv_h = (float)G / (S_HI - S_LO);

    const float sv = s[j];
    int g = (int)((sv - S_LO) * inv_h);
    g = max(0, min(G - 1, g));
    const float c = S_LO + ((float)g + 0.5f) * h;
    atomicAdd(&g_SH[2 * g],     1.0f);
    atomicAdd(&g_SH[2 * g + 1], sv - c);

    const float yv = y[j];
    int q = (int)(yv * 65536.0f);
    q = max(0, min(YB - 1, q));
    atomicAdd(&g_YC[q], 1.0f);
    atomicAdd(&g_YS[q], yv);
}

// --------------------------------------------------------------------------
// Per-1024-bin chunk sums of y counts.
__global__ void __launch_bounds__(1024)
k_scan_a()
{
    __shared__ float sm[1024];
    const int t = threadIdx.x;
    sm[t] = g_YC[blockIdx.x * 1024 + t];
    __syncthreads();
    for (int off = 512; off > 0; off >>= 1) {
        if (t < off) sm[t] += sm[t + off];
        __syncthreads();
    }
    if (t == 0) g_CS[blockIdx.x] = sm[0];
}

// Exclusive suffix over the 64 chunk sums.
__global__ void k_scan_b()
{
    const int b = threadIdx.x;
    if (b < YBLK) {
        float acc = 0.0f;
        for (int b2 = b + 1; b2 < YBLK; b2++) acc += g_CS[b2];
        g_CSX[b] = acc;
    }
}

// --------------------------------------------------------------------------
// Binned sigmoid convolution: thread = element j, blockIdx.y = bin split.
__global__ void __launch_bounds__(TPB)
k_rank(const float* __restrict__ s, int n)
{
    const int j     = blockIdx.x * TPB + threadIdx.x;
    const int split = blockIdx.y;

    __shared__ float2 sh[GCHUNK];
    for (int t = threadIdx.x; t < GCHUNK; t += TPB)
        sh[t] = reinterpret_cast<const float2*>(g_SH)[split * GCHUNK + t];
    __syncthreads();

    const float h  = (S_HI - S_LO) / (float)G;
    const float hh = 0.5f * h;
    const float sv = (j < n) ? s[j] : 0.0f;
    // x_t = 0.5*(s_j - c_{g0+t});  c_g = S_LO + (g+0.5)*h
    const float x0 = 0.5f * sv
                   - 0.5f * (S_LO + ((float)(split * GCHUNK) + 0.5f) * h);

    float acc = 0.0f;
    float tf  = 0.0f;
    #pragma unroll 8
    for (int t = 0; t < GCHUNK; t++) {
        const float  x  = fmaf(tf, -hh, x0);
        tf += 1.0f;
        const float  th = tanh_approx(x);
        const float2 hs = sh[t];
        const float  sg = fmaf(0.5f, th, 0.5f);          // sigmoid
        const float  t2 = th * th;
        const float  sp = fmaf(-0.25f, t2, 0.25f);       // sigmoid'
        acc = fmaf(hs.x, sg, acc);
        acc = fmaf(-hs.y, sp, acc);
    }

    if (j < n) g_rankP[split * MAXN + j] = acc;
}

// --------------------------------------------------------------------------
// Exact-rank IDCG from the y histogram.
__global__ void __launch_bounds__(1024)
k_idcg()
{
    __shared__ float sc[1024];
    const int t = threadIdx.x;
    const int q = blockIdx.x * 1024 + t;

    const float c = g_YC[q];
    sc[t] = c;
    __syncthreads();
    // inclusive suffix scan over the 1024-bin chunk
    for (int off = 1; off < 1024; off <<= 1) {
        float add = (t + off < 1024) ? sc[t + off] : 0.0f;
        __syncthreads();
        sc[t] += add;
        __syncthreads();
    }
    const float above = g_CSX[blockIdx.x] + (sc[t] - c);  // strictly higher bins

    float idg  = 0.0f;
    float ysum = g_YS[q];
    const int ci = (int)c;
    if (ci > 0) {
        const float ybar = ysum / (float)ci;
        for (int k = 1; k <= ci; k++) {
            const float rank = above + (float)k;          // exact ideal rank
            idg += ybar / __log2f(rank + 1.0f);
        }
    }

    // block reduction
    __shared__ float ri[1024], rs[1024];
    ri[t] = idg; rs[t] = ysum;
    __syncthreads();
    for (int off = 512; off > 0; off >>= 1) {
        if (t < off) { ri[t] += ri[t + off]; rs[t] += rs[t + off]; }
        __syncthreads();
    }
    if (t == 0) { g_idcgP[blockIdx.x] = ri[0]; g_sumyP[blockIdx.x] = rs[0]; }
}

// --------------------------------------------------------------------------
// Per-element DCG from rank partials.
__global__ void __launch_bounds__(TPB)
k_dcg(const float* __restrict__ y, int n)
{
    const int j = blockIdx.x * TPB + threadIdx.x;

    float dcg = 0.0f;
    if (j < n) {
        float acc = 0.0f;
        #pragma unroll
        for (int sp = 0; sp < GSPLIT; sp++) acc += g_rankP[sp * MAXN + j];
        const float rank = 1.0f + acc;
        dcg = y[j] / __log2f(rank + 1.0f);
    }

    __shared__ float rd[TPB];
    rd[threadIdx.x] = dcg;
    __syncthreads();
    for (int off = TPB / 2; off > 0; off >>= 1) {
        if (threadIdx.x < off) rd[threadIdx.x] += rd[threadIdx.x + off];
        __syncthreads();
    }
    if (threadIdx.x == 0) g_dcgP[blockIdx.x] = rd[0];
}

// --------------------------------------------------------------------------
__global__ void __launch_bounds__(TPB)
k_final(float* __restrict__ out, int jblocks)
{
    __shared__ float rd[TPB], ri[TPB], rs[TPB];
    float d = 0.0f, i = 0.0f, sY = 0.0f;
    for (int b = threadIdx.x; b < jblocks; b += TPB) d += g_dcgP[b];
    if (threadIdx.x < YBLK) { i = g_idcgP[threadIdx.x]; sY = g_sumyP[threadIdx.x]; }
    rd[threadIdx.x] = d; ri[threadIdx.x] = i; rs[threadIdx.x] = sY;
    __syncthreads();
    for (int off = TPB / 2; off > 0; off >>= 1) {
        if (threadIdx.x < off) {
            rd[threadIdx.x] += rd[threadIdx.x + off];
            ri[threadIdx.x] += ri[threadIdx.x + off];
            rs[threadIdx.x] += rs[threadIdx.x + off];
        }
        __syncthreads();
    }
    if (threadIdx.x == 0) {
        const float ndcg = rd[0] / (ri[0] + 1e-8f);
        const float loss = 1.0f - ndcg;
        out[0] = (rs[0] < 1.0f) ? 0.0f : loss;
    }
}

// --------------------------------------------------------------------------
extern "C" void kernel_launch(void* const* d_in, const int* in_sizes, int n_in,
                              void* d_out, int out_size)
{
    const float* s = (const float*)d_in[0];   // logits
    const float* y = (const float*)d_in[1];   // targets
    float* out = (float*)d_out;
    const int n = in_sizes[0];

    const int jblocks = (n + TPB - 1) / TPB;

    k_zero<<<64, TPB>>>();
    k_hist<<<jblocks, TPB>>>(s, y, n);
    k_scan_a<<<YBLK, 1024>>>();
    k_scan_b<<<1, 64>>>();
    dim3 gr(jblocks, GSPLIT);
    k_rank<<<gr, TPB>>>(s, n);
    k_idcg<<<YBLK, 1024>>>();
    k_dcg<<<jblocks, TPB>>>(y, n);
    k_final<<<1, TPB>>>(out, jblocks);
}